// round 5
// baseline (speedup 1.0000x reference)
#include <cuda_runtime.h>
#include <cstdint>
#include <cmath>

#define B_ 4
#define S_ 2048
#define H_ 12
#define D_ 64
#define BM 128         // q rows per CTA (8 warps x m=16)
#define BN 32          // k cols per tile
#define NKT (S_ / BN)  // 64 k-tiles
#define KST 68         // K stage row stride (words): B-frag bank = 4g+tg, conflict-free
#define VST 72         // V stage row stride (words): B-frag bank = 8tg+g, conflict-free
#define PST 36         // P row stride (words): A-frag bank = 4g+tg, conflict-free

#define KSTAGE (BN * KST)   // floats per K stage
#define VSTAGE (BN * VST)
#define SMEM_BYTES ((2 * KSTAGE + 2 * VSTAGE) * 4 + 8 * 16 * PST * 4)

__device__ __forceinline__ uint32_t f2tf(float x) {
    uint32_t y;
    asm("cvt.rna.tf32.f32 %0, %1;" : "=r"(y) : "f"(x));
    return y;
}

__device__ __forceinline__ void cp16(void* dst_smem, const void* src_gmem) {
    unsigned d = (unsigned)__cvta_generic_to_shared(dst_smem);
    asm volatile("cp.async.cg.shared.global [%0], [%1], 16;\n" :: "r"(d), "l"(src_gmem));
}

__device__ __forceinline__ void mma8(float* c, const uint32_t* a, const uint32_t* b) {
    asm volatile(
        "mma.sync.aligned.m16n8k8.row.col.f32.tf32.tf32.f32 "
        "{%0,%1,%2,%3}, {%4,%5,%6,%7}, {%8,%9}, {%0,%1,%2,%3};"
        : "+f"(c[0]), "+f"(c[1]), "+f"(c[2]), "+f"(c[3])
        : "r"(a[0]), "r"(a[1]), "r"(a[2]), "r"(a[3]), "r"(b[0]), "r"(b[1]));
}

__global__ void __launch_bounds__(256, 2)
fa2_tf32_kernel(const float* __restrict__ q, const float* __restrict__ k,
                const float* __restrict__ v, const float* __restrict__ bias,
                float* __restrict__ out)
{
    extern __shared__ float smem[];
    float* Ks = smem;                          // [2][KSTAGE] raw fp32
    float* Vs = smem + 2 * KSTAGE;             // [2][VSTAGE] raw fp32
    uint32_t* Ps = (uint32_t*)(smem + 2 * KSTAGE + 2 * VSTAGE); // [8][16*PST]

    const int tid  = threadIdx.x;
    const int w    = tid >> 5;    // 0..7
    const int lane = tid & 31;
    const int g    = lane >> 2;   // 0..7
    const int tg   = lane & 3;    // 0..3

    const int qt = blockIdx.x;
    const int bh = blockIdx.y;
    const int b  = bh / H_;
    const int h  = bh % H_;
    const int q0 = qt * BM;

    const float scale = 0.125f;   // 1/sqrt(64)

    const float* kbase = k + ((size_t)b * S_) * (H_ * D_) + h * D_;
    const float* vbase = v + ((size_t)b * S_) * (H_ * D_) + h * D_;

    // ---- Q tile fragments (RNA tf32): warp covers rows q0 + w*16 + {0..15} ----
    uint32_t qa[8][4];
    {
        const float* qr0 = q + ((size_t)b * S_ + q0 + w * 16 + g)     * (H_ * D_) + h * D_;
        const float* qr1 = q + ((size_t)b * S_ + q0 + w * 16 + g + 8) * (H_ * D_) + h * D_;
        #pragma unroll
        for (int kf = 0; kf < 8; kf++) {
            const int c0 = kf * 8 + tg;
            qa[kf][0] = f2tf(qr0[c0]);
            qa[kf][1] = f2tf(qr1[c0]);
            qa[kf][2] = f2tf(qr0[c0 + 4]);
            qa[kf][3] = f2tf(qr1[c0 + 4]);
        }
    }

    float o[8][4];
    #pragma unroll
    for (int nf = 0; nf < 8; nf++)
        #pragma unroll
        for (int c = 0; c < 4; c++) o[nf][c] = 0.f;

    float m_[2] = {-INFINITY, -INFINITY};
    float l_[2] = {0.f, 0.f};

    const float* bbase = bias + (((size_t)b * H_ + h) * S_ + q0 + w * 16) * (size_t)S_;

    // ---- prologue: prefetch tile 0 into stage 0 ----
    {
        #pragma unroll
        for (int i = 0; i < 2; i++) {
            const int c   = tid + i * 256;
            const int row = c >> 4;
            const int col = (c & 15) * 4;
            cp16(&Ks[row * KST + col], kbase + (size_t)row * (H_ * D_) + col);
            cp16(&Vs[row * VST + col], vbase + (size_t)row * (H_ * D_) + col);
        }
        asm volatile("cp.async.commit_group;\n" ::);
    }

    #pragma unroll 1
    for (int kt = 0; kt < NKT; kt++) {
        const int k0 = kt * BN;
        const int s  = kt & 1;
        float* Kf = Ks + s * KSTAGE;
        float* Vf = Vs + s * VSTAGE;

        asm volatile("cp.async.wait_group 0;\n" ::);
        __syncthreads();

        // ---- prefetch tile kt+1 into stage s^1 ----
        if (kt + 1 < NKT) {
            const int k0n = (kt + 1) * BN;
            float* Kn = Ks + (s ^ 1) * KSTAGE;
            float* Vn = Vs + (s ^ 1) * VSTAGE;
            #pragma unroll
            for (int i = 0; i < 2; i++) {
                const int c   = tid + i * 256;
                const int row = c >> 4;
                const int col = (c & 15) * 4;
                cp16(&Kn[row * KST + col], kbase + (size_t)(k0n + row) * (H_ * D_) + col);
                cp16(&Vn[row * VST + col], vbase + (size_t)(k0n + row) * (H_ * D_) + col);
            }
            asm volatile("cp.async.commit_group;\n" ::);
        }

        // ---- bias loads issued early (overlap with QK mma) ----
        float2 bz[2][4];
        #pragma unroll
        for (int rb = 0; rb < 2; rb++)
            #pragma unroll
            for (int nf = 0; nf < 4; nf++)
                bz[rb][nf] = *(const float2*)(bbase + (size_t)(rb * 8 + g) * S_
                                              + k0 + nf * 8 + 2 * tg);

        // ---- S = Q @ K^T : per-warp 16x32 tile ----
        float sacc[4][4];
        #pragma unroll
        for (int nf = 0; nf < 4; nf++)
            #pragma unroll
            for (int c = 0; c < 4; c++) sacc[nf][c] = 0.f;

        #pragma unroll
        for (int kf = 0; kf < 8; kf++) {
            #pragma unroll
            for (int nf = 0; nf < 4; nf++) {
                uint32_t bk[2];
                bk[0] = f2tf(Kf[(nf * 8 + g) * KST + kf * 8 + tg]);
                bk[1] = f2tf(Kf[(nf * 8 + g) * KST + kf * 8 + tg + 4]);
                mma8(sacc[nf], qa[kf], bk);
            }
        }

        // ---- scale + bias; sacc[nf][2rb+j] = row rb*8+g, col 2tg+j ----
        #pragma unroll
        for (int nf = 0; nf < 4; nf++)
            #pragma unroll
            for (int rb = 0; rb < 2; rb++) {
                sacc[nf][2 * rb]     = fmaf(sacc[nf][2 * rb],     scale, bz[rb][nf].x);
                sacc[nf][2 * rb + 1] = fmaf(sacc[nf][2 * rb + 1], scale, bz[rb][nf].y);
            }

        // ---- online softmax (2 rows per thread) ----
        float a_[2];
        #pragma unroll
        for (int rb = 0; rb < 2; rb++) {
            float mx = -INFINITY;
            #pragma unroll
            for (int nf = 0; nf < 4; nf++)
                mx = fmaxf(mx, fmaxf(sacc[nf][2 * rb], sacc[nf][2 * rb + 1]));
            mx = fmaxf(mx, __shfl_xor_sync(0xffffffffu, mx, 1));
            mx = fmaxf(mx, __shfl_xor_sync(0xffffffffu, mx, 2));
            const float nm = fmaxf(m_[rb], mx);
            a_[rb] = __expf(m_[rb] - nm);
            m_[rb] = nm;
        }

        float rs[2] = {0.f, 0.f};
        #pragma unroll
        for (int nf = 0; nf < 4; nf++)
            #pragma unroll
            for (int rb = 0; rb < 2; rb++) {
                float p0 = __expf(sacc[nf][2 * rb]     - m_[rb]);
                float p1 = __expf(sacc[nf][2 * rb + 1] - m_[rb]);
                uint32_t u0 = f2tf(p0), u1 = f2tf(p1);
                sacc[nf][2 * rb]     = __uint_as_float(u0);
                sacc[nf][2 * rb + 1] = __uint_as_float(u1);
                rs[rb] += __uint_as_float(u0) + __uint_as_float(u1);
            }
        #pragma unroll
        for (int rb = 0; rb < 2; rb++) {
            rs[rb] += __shfl_xor_sync(0xffffffffu, rs[rb], 1);
            rs[rb] += __shfl_xor_sync(0xffffffffu, rs[rb], 2);
            l_[rb] = l_[rb] * a_[rb] + rs[rb];
        }

        #pragma unroll
        for (int nf = 0; nf < 8; nf++)
            #pragma unroll
            for (int rb = 0; rb < 2; rb++) {
                o[nf][2 * rb]     *= a_[rb];
                o[nf][2 * rb + 1] *= a_[rb];
            }

        // ---- P -> warp-private smem ----
        uint32_t* Pw = Ps + w * (16 * PST);
        #pragma unroll
        for (int rb = 0; rb < 2; rb++)
            #pragma unroll
            for (int nf = 0; nf < 4; nf++)
                *(uint2*)&Pw[(rb * 8 + g) * PST + nf * 8 + 2 * tg] =
                    make_uint2(__float_as_uint(sacc[nf][2 * rb]),
                               __float_as_uint(sacc[nf][2 * rb + 1]));
        __syncwarp();

        // ---- O += P @ V ----
        #pragma unroll
        for (int kf = 0; kf < 4; kf++) {
            uint32_t pa[4];
            pa[0] = Pw[(g)     * PST + kf * 8 + tg];
            pa[1] = Pw[(g + 8) * PST + kf * 8 + tg];
            pa[2] = Pw[(g)     * PST + kf * 8 + tg + 4];
            pa[3] = Pw[(g + 8) * PST + kf * 8 + tg + 4];
            #pragma unroll
            for (int nf = 0; nf < 8; nf++) {
                uint32_t vb[2];
                vb[0] = f2tf(Vf[(kf * 8 + tg)     * VST + nf * 8 + g]);
                vb[1] = f2tf(Vf[(kf * 8 + tg + 4) * VST + nf * 8 + g]);
                mma8(o[nf], pa, vb);
            }
        }
    }

    // ---- normalize and write out ----
    const float inv0 = 1.f / l_[0];
    const float inv1 = 1.f / l_[1];
    const int r0 = q0 + w * 16 + g;
    float* op0 = out + ((size_t)b * S_ + r0)     * (H_ * D_) + h * D_;
    float* op1 = out + ((size_t)b * S_ + r0 + 8) * (H_ * D_) + h * D_;
    #pragma unroll
    for (int nf = 0; nf < 8; nf++) {
        *(float2*)(op0 + nf * 8 + 2 * tg) =
            make_float2(o[nf][0] * inv0, o[nf][1] * inv0);
        *(float2*)(op1 + nf * 8 + 2 * tg) =
            make_float2(o[nf][2] * inv1, o[nf][3] * inv1);
    }
}

extern "C" void kernel_launch(void* const* d_in, const int* in_sizes, int n_in,
                              void* d_out, int out_size)
{
    const float* q    = (const float*)d_in[0];
    const float* k    = (const float*)d_in[1];
    const float* v    = (const float*)d_in[2];
    const float* bias = (const float*)d_in[3];
    float* out = (float*)d_out;
    (void)in_sizes; (void)n_in; (void)out_size;

    cudaFuncSetAttribute(fa2_tf32_kernel,
                         cudaFuncAttributeMaxDynamicSharedMemorySize, SMEM_BYTES);

    dim3 grid(S_ / BM, B_ * H_);
    fa2_tf32_kernel<<<grid, 256, SMEM_BYTES>>>(q, k, v, bias, out);
}

// round 10
// speedup vs baseline: 1.1745x; 1.1745x over previous
#include <cuda_runtime.h>
#include <cstdint>
#include <cmath>

#define B_ 4
#define S_ 2048
#define H_ 12
#define D_ 64
#define BM 128         // q rows per CTA (4 warps x m=32)
#define BN 32          // k cols per tile
#define NKT (S_ / BN)  // 64 k-tiles
#define KST 68         // K stage row stride (words): B-frag bank = 4g+tg, conflict-free
#define VST 72         // V stage row stride (words): B-frag bank = 8tg+g, conflict-free
#define PST 36         // P row stride (words): A-frag bank = 4g+tg, conflict-free

#define KSTAGE (BN * KST)   // floats per K stage (2176)
#define VSTAGE (BN * VST)   // floats per V stage (2304)
#define SMEM_BYTES ((3 * KSTAGE + 3 * VSTAGE) * 4 + 4 * BN * PST * 4)  // 72192

__device__ __forceinline__ uint32_t f2tf(float x) {
    uint32_t y;
    asm("cvt.rna.tf32.f32 %0, %1;" : "=r"(y) : "f"(x));
    return y;
}

__device__ __forceinline__ void cp16(void* dst_smem, const void* src_gmem) {
    unsigned d = (unsigned)__cvta_generic_to_shared(dst_smem);
    asm volatile("cp.async.cg.shared.global [%0], [%1], 16;\n" :: "r"(d), "l"(src_gmem));
}

__device__ __forceinline__ void mma8(float* c, const uint32_t* a, const uint32_t* b) {
    asm volatile(
        "mma.sync.aligned.m16n8k8.row.col.f32.tf32.tf32.f32 "
        "{%0,%1,%2,%3}, {%4,%5,%6,%7}, {%8,%9}, {%0,%1,%2,%3};"
        : "+f"(c[0]), "+f"(c[1]), "+f"(c[2]), "+f"(c[3])
        : "r"(a[0]), "r"(a[1]), "r"(a[2]), "r"(a[3]), "r"(b[0]), "r"(b[1]));
}

__global__ void __launch_bounds__(128)
fa2_tf32_kernel(const float* __restrict__ q, const float* __restrict__ k,
                const float* __restrict__ v, const float* __restrict__ bias,
                float* __restrict__ out)
{
    extern __shared__ float smem[];
    float* Ks = smem;                              // [3][KSTAGE]
    float* Vs = smem + 3 * KSTAGE;                 // [3][VSTAGE]
    uint32_t* Ps = (uint32_t*)(smem + 3 * KSTAGE + 3 * VSTAGE); // [4][32*PST]

    const int tid  = threadIdx.x;
    const int w    = tid >> 5;
    const int lane = tid & 31;
    const int g    = lane >> 2;   // 0..7
    const int tg   = lane & 3;    // 0..3

    const int qt = blockIdx.x;
    const int bh = blockIdx.y;
    const int b  = bh / H_;
    const int h  = bh % H_;
    const int q0 = qt * BM;

    const float scale = 0.125f;   // 1/sqrt(64)

    const float* kbase = k + ((size_t)b * S_) * (H_ * D_) + h * D_;
    const float* vbase = v + ((size_t)b * S_) * (H_ * D_) + h * D_;
    const float* bbase = bias + (((size_t)b * H_ + h) * S_ + q0 + w * 32) * (size_t)S_;

    // ---- Q tile fragments (RNA tf32), rows q0 + w*32 + {0..31} ----
    uint32_t qa[8][8];
    {
        const float* qr[4];
        #pragma unroll
        for (int rb = 0; rb < 4; rb++)
            qr[rb] = q + ((size_t)b * S_ + q0 + w * 32 + rb * 8 + g) * (H_ * D_) + h * D_;
        #pragma unroll
        for (int kf = 0; kf < 8; kf++) {
            const int c0 = kf * 8 + tg;
            qa[kf][0] = f2tf(qr[0][c0]);
            qa[kf][1] = f2tf(qr[1][c0]);
            qa[kf][2] = f2tf(qr[0][c0 + 4]);
            qa[kf][3] = f2tf(qr[1][c0 + 4]);
            qa[kf][4] = f2tf(qr[2][c0]);
            qa[kf][5] = f2tf(qr[3][c0]);
            qa[kf][6] = f2tf(qr[2][c0 + 4]);
            qa[kf][7] = f2tf(qr[3][c0 + 4]);
        }
    }

    float o[8][8];
    #pragma unroll
    for (int nf = 0; nf < 8; nf++)
        #pragma unroll
        for (int c = 0; c < 8; c++) o[nf][c] = 0.f;

    float m_[4] = {-INFINITY, -INFINITY, -INFINITY, -INFINITY};
    float l_[4] = {0.f, 0.f, 0.f, 0.f};

    // ---- prologue: cp.async tile 0 -> stage 0 (group), tile 1 -> stage 1 (group) ----
    #pragma unroll
    for (int i = 0; i < 4; i++) {
        const int c   = tid + i * 128;
        const int row = c >> 4;
        const int col = (c & 15) * 4;
        cp16(&Ks[row * KST + col], kbase + (size_t)row * (H_ * D_) + col);
        cp16(&Vs[row * VST + col], vbase + (size_t)row * (H_ * D_) + col);
    }
    asm volatile("cp.async.commit_group;\n" ::);
    #pragma unroll
    for (int i = 0; i < 4; i++) {
        const int c   = tid + i * 128;
        const int row = c >> 4;
        const int col = (c & 15) * 4;
        cp16(&Ks[KSTAGE + row * KST + col], kbase + (size_t)(BN + row) * (H_ * D_) + col);
        cp16(&Vs[VSTAGE + row * VST + col], vbase + (size_t)(BN + row) * (H_ * D_) + col);
    }
    asm volatile("cp.async.commit_group;\n" ::);

    // ---- bias(0) -> bz ----
    float2 bz[4][4];
    #pragma unroll
    for (int rb = 0; rb < 4; rb++)
        #pragma unroll
        for (int nf = 0; nf < 4; nf++)
            bz[rb][nf] = *(const float2*)(bbase + (size_t)(rb * 8 + g) * S_
                                          + nf * 8 + 2 * tg);

    // ---- wait tile 0, compute S(0) = Q @ K(0)^T into sacc ----
    float sacc[4][8];
    #pragma unroll
    for (int nf = 0; nf < 4; nf++)
        #pragma unroll
        for (int c = 0; c < 8; c++) sacc[nf][c] = 0.f;

    asm volatile("cp.async.wait_group 1;\n" ::);
    __syncthreads();
    #pragma unroll
    for (int kf = 0; kf < 8; kf++) {
        #pragma unroll
        for (int nf = 0; nf < 4; nf++) {
            uint32_t bk[2];
            bk[0] = f2tf(Ks[(nf * 8 + g) * KST + kf * 8 + tg]);
            bk[1] = f2tf(Ks[(nf * 8 + g) * KST + kf * 8 + tg + 4]);
            mma8(&sacc[nf][0], &qa[kf][0], bk);
            mma8(&sacc[nf][4], &qa[kf][4], bk);
        }
    }

    int s_cur = 0;

    #pragma unroll 1
    for (int kt = 0; kt < NKT; kt++) {
        int s_nxt = s_cur + 1; if (s_nxt == 3) s_nxt = 0;
        int s_pf  = s_nxt + 1; if (s_pf  == 3) s_pf  = 0;

        // ---- 1. softmax on S(kt): scale + bias, max, exp, rescale o ----
        #pragma unroll
        for (int nf = 0; nf < 4; nf++)
            #pragma unroll
            for (int rb = 0; rb < 4; rb++) {
                sacc[nf][2 * rb]     = fmaf(sacc[nf][2 * rb],     scale, bz[rb][nf].x);
                sacc[nf][2 * rb + 1] = fmaf(sacc[nf][2 * rb + 1], scale, bz[rb][nf].y);
            }

        float a_[4];
        #pragma unroll
        for (int rb = 0; rb < 4; rb++) {
            float mx = -INFINITY;
            #pragma unroll
            for (int nf = 0; nf < 4; nf++)
                mx = fmaxf(mx, fmaxf(sacc[nf][2 * rb], sacc[nf][2 * rb + 1]));
            mx = fmaxf(mx, __shfl_xor_sync(0xffffffffu, mx, 1));
            mx = fmaxf(mx, __shfl_xor_sync(0xffffffffu, mx, 2));
            const float nm = fmaxf(m_[rb], mx);
            a_[rb] = __expf(m_[rb] - nm);
            m_[rb] = nm;
        }

        float rs[4] = {0.f, 0.f, 0.f, 0.f};
        #pragma unroll
        for (int nf = 0; nf < 4; nf++)
            #pragma unroll
            for (int rb = 0; rb < 4; rb++) {
                float p0 = __expf(sacc[nf][2 * rb]     - m_[rb]);
                float p1 = __expf(sacc[nf][2 * rb + 1] - m_[rb]);
                uint32_t u0 = f2tf(p0), u1 = f2tf(p1);
                sacc[nf][2 * rb]     = __uint_as_float(u0);
                sacc[nf][2 * rb + 1] = __uint_as_float(u1);
                rs[rb] += __uint_as_float(u0) + __uint_as_float(u1);
            }
        #pragma unroll
        for (int rb = 0; rb < 4; rb++) {
            rs[rb] += __shfl_xor_sync(0xffffffffu, rs[rb], 1);
            rs[rb] += __shfl_xor_sync(0xffffffffu, rs[rb], 2);
            l_[rb] = l_[rb] * a_[rb] + rs[rb];
        }

        #pragma unroll
        for (int nf = 0; nf < 8; nf++)
            #pragma unroll
            for (int rb = 0; rb < 4; rb++) {
                o[nf][2 * rb]     *= a_[rb];
                o[nf][2 * rb + 1] *= a_[rb];
            }

        // ---- 2. P(kt) -> warp-private smem; sacc now dead ----
        uint32_t* Pw = Ps + w * (BN * PST);
        #pragma unroll
        for (int rb = 0; rb < 4; rb++)
            #pragma unroll
            for (int nf = 0; nf < 4; nf++)
                *(uint2*)&Pw[(rb * 8 + g) * PST + nf * 8 + 2 * tg] =
                    make_uint2(__float_as_uint(sacc[nf][2 * rb]),
                               __float_as_uint(sacc[nf][2 * rb + 1]));
        __syncwarp();

        // ---- 3. bias(kt+1) -> bz (consumed next iteration) ----
        if (kt + 1 < NKT) {
            const int k0n = (kt + 1) * BN;
            #pragma unroll
            for (int rb = 0; rb < 4; rb++)
                #pragma unroll
                for (int nf = 0; nf < 4; nf++)
                    bz[rb][nf] = *(const float2*)(bbase + (size_t)(rb * 8 + g) * S_
                                                  + k0n + nf * 8 + 2 * tg);
        }

        // ---- 4. wait for K/V(kt+1); barrier closes all reads of stage s_pf ----
        asm volatile("cp.async.wait_group 0;\n" ::);
        __syncthreads();

        // ---- 5. prefetch tile kt+2 into stage s_pf (AFTER barrier: no WAR race) ----
        if (kt + 2 < NKT) {
            const int k0n = (kt + 2) * BN;
            float* Kn2 = Ks + s_pf * KSTAGE;
            float* Vn2 = Vs + s_pf * VSTAGE;
            #pragma unroll
            for (int i = 0; i < 4; i++) {
                const int c   = tid + i * 128;
                const int row = c >> 4;
                const int col = (c & 15) * 4;
                cp16(&Kn2[row * KST + col], kbase + (size_t)(k0n + row) * (H_ * D_) + col);
                cp16(&Vn2[row * VST + col], vbase + (size_t)(k0n + row) * (H_ * D_) + col);
            }
            asm volatile("cp.async.commit_group;\n" ::);
        }

        // ---- 6. interleaved: QK(kt+1) -> sacc  |  O += P(kt) @ V(kt) ----
        const bool doQK = (kt + 1 < NKT);
        const float* Kn = Ks + s_nxt * KSTAGE;
        const float* Vf = Vs + s_cur * VSTAGE;

        if (doQK) {
            #pragma unroll
            for (int nf = 0; nf < 4; nf++)
                #pragma unroll
                for (int c = 0; c < 8; c++) sacc[nf][c] = 0.f;
        }

        #pragma unroll
        for (int blk = 0; blk < 4; blk++) {
            if (doQK) {
                #pragma unroll
                for (int kk = 0; kk < 2; kk++) {
                    const int kf = blk * 2 + kk;
                    #pragma unroll
                    for (int nf = 0; nf < 4; nf++) {
                        uint32_t bk[2];
                        bk[0] = f2tf(Kn[(nf * 8 + g) * KST + kf * 8 + tg]);
                        bk[1] = f2tf(Kn[(nf * 8 + g) * KST + kf * 8 + tg + 4]);
                        mma8(&sacc[nf][0], &qa[kf][0], bk);
                        mma8(&sacc[nf][4], &qa[kf][4], bk);
                    }
                }
            }
            // PV block: kf' = blk
            uint32_t pa[8];
            pa[0] = Pw[(g)      * PST + blk * 8 + tg];
            pa[1] = Pw[(g + 8)  * PST + blk * 8 + tg];
            pa[2] = Pw[(g)      * PST + blk * 8 + tg + 4];
            pa[3] = Pw[(g + 8)  * PST + blk * 8 + tg + 4];
            pa[4] = Pw[(g + 16) * PST + blk * 8 + tg];
            pa[5] = Pw[(g + 24) * PST + blk * 8 + tg];
            pa[6] = Pw[(g + 16) * PST + blk * 8 + tg + 4];
            pa[7] = Pw[(g + 24) * PST + blk * 8 + tg + 4];
            #pragma unroll
            for (int nf = 0; nf < 8; nf++) {
                uint32_t vb[2];
                vb[0] = f2tf(Vf[(blk * 8 + tg)     * VST + nf * 8 + g]);
                vb[1] = f2tf(Vf[(blk * 8 + tg + 4) * VST + nf * 8 + g]);
                mma8(&o[nf][0], &pa[0], vb);
                mma8(&o[nf][4], &pa[4], vb);
            }
        }

        s_cur = s_nxt;
    }

    // ---- normalize and write out ----
    float inv[4];
    #pragma unroll
    for (int rb = 0; rb < 4; rb++) inv[rb] = 1.f / l_[rb];

    #pragma unroll
    for (int rb = 0; rb < 4; rb++) {
        const int r = q0 + w * 32 + rb * 8 + g;
        float* op = out + ((size_t)b * S_ + r) * (H_ * D_) + h * D_;
        #pragma unroll
        for (int nf = 0; nf < 8; nf++)
            *(float2*)(op + nf * 8 + 2 * tg) =
                make_float2(o[nf][2 * rb] * inv[rb], o[nf][2 * rb + 1] * inv[rb]);
    }
}

extern "C" void kernel_launch(void* const* d_in, const int* in_sizes, int n_in,
                              void* d_out, int out_size)
{
    const float* q    = (const float*)d_in[0];
    const float* k    = (const float*)d_in[1];
    const float* v    = (const float*)d_in[2];
    const float* bias = (const float*)d_in[3];
    float* out = (float*)d_out;
    (void)in_sizes; (void)n_in; (void)out_size;

    cudaFuncSetAttribute(fa2_tf32_kernel,
                         cudaFuncAttributeMaxDynamicSharedMemorySize, SMEM_BYTES);

    dim3 grid(S_ / BM, B_ * H_);
    fa2_tf32_kernel<<<grid, 128, SMEM_BYTES>>>(q, k, v, bias, out);
}